// round 10
// baseline (speedup 1.0000x reference)
#include <cuda_runtime.h>
#include <cstdint>

// MoEVM_62380105007239 — soft-ALU over one-hot byte encodings. FINAL (R6).
//
// Math: inputs are exact one-hot byte distributions, so the reference's
// SCALE=100 softmax pipeline collapses to u32 add (the 4-byte little-endian
// nibble carry chain == 32-bit add) and bytewise XOR. Output per byte slot:
// 1.0 at the result byte, exp(-100) (fp32 subnormal) at the 30 bytes sharing
// its high or low nibble, 0 elsewhere (exp(-200) underflows fp32).
//
// Structure (best of 9 measured variants, 75.8us / 80.1% DRAM):
//  - warp pair (g, role): role 0 reads a[e] and writes the add-output[e],
//    role 1 reads b[e] and writes the xor-output[e] -> each warp owns exactly
//    one sequential 4 KB read stream and one sequential 4 KB write stream.
//  - 2-element depth-1 software pipeline: element e1's 8 loads are issued as
//    a front-loaded batch (MLP=8) BEFORE element e0's 8 stores, keeping a
//    read and a write stream concurrently in flight at the DRAM controller.
//  - FMA decode (one-hot dot index == index) keeps the alu pipe light;
//    __ldcs/__stcs since nothing is ever reused.
// Measured floor: ~6.33 TB/s (~80% of HBM spec) is the controller ceiling
// for this mix; traffic (537 MB) is at its algorithmic minimum.

static __device__ __forceinline__ float onehot_val(int j, int s, float tiny) {
    if (j == s) return 1.0f;
    if (((j ^ s) & 0xF0) == 0 || ((j ^ s) & 0x0F) == 0) return tiny;
    return 0.0f;
}

// Decode 8 raw float4s (one-hot dot index == the index) into a packed u32.
static __device__ __forceinline__ unsigned decode_pack(const float4* x, int lane) {
    float acc[4] = {0.f, 0.f, 0.f, 0.f};
    #pragma unroll
    for (int r = 0; r < 8; r++) {
        const float j = (float)(lane * 4 + 128 * (r & 1));
        acc[r >> 1] += x[r].x * j + x[r].y * (j + 1.f)
                     + x[r].z * (j + 2.f) + x[r].w * (j + 3.f);
    }
    unsigned iv = (unsigned)(int)acc[0]
                | ((unsigned)(int)acc[1] << 8)
                | ((unsigned)(int)acc[2] << 16)
                | ((unsigned)(int)acc[3] << 24);
    return __reduce_or_sync(0xFFFFFFFFu, iv);
}

// Expand packed result to 4 KB near-one-hot output (8 coalesced STG.128).
static __device__ __forceinline__ void store_out(float4* dst, unsigned res, int lane) {
    const float TINY = 3.7200760e-44f;             // expf(-100), subnormal
    #pragma unroll
    for (int r = 0; r < 8; r++) {
        const int j  = lane * 4 + 128 * (r & 1);
        const int sb = (int)((res >> ((r >> 1) * 8)) & 255u);
        float4 o;
        o.x = onehot_val(j    , sb, TINY);
        o.y = onehot_val(j + 1, sb, TINY);
        o.z = onehot_val(j + 2, sb, TINY);
        o.w = onehot_val(j + 3, sb, TINY);
        __stcs(dst + lane + 32 * r, o);
    }
}

__global__ void __launch_bounds__(256, 4) moe_alu_kernel(
    const float4* __restrict__ a4,
    const float4* __restrict__ b4,
    float4* __restrict__ o4,
    int B)
{
    __shared__ unsigned sm[2][4][2];         // [phase][pair g][role]

    const int wid  = threadIdx.x >> 5;       // 0..7
    const int lane = threadIdx.x & 31;
    const int g    = wid >> 1;               // pair id 0..3
    const int role = wid & 1;                // 0: a/add-half, 1: b/xor-half
    const int e0   = blockIdx.x * 8 + g * 2; // this pair's two elements
    const int e1   = e0 + 1;
    if (e0 >= B) return;                     // whole block uniform for full B
    const bool has1 = (e1 < B);

    const float4* __restrict__ srcbase = (role == 0) ? a4 : b4;

    // ── Phase 0 decode: element e0 ──
    {
        const float4* __restrict__ s0 = srcbase + (size_t)e0 * 256;
        float4 x[8];
        #pragma unroll
        for (int r = 0; r < 8; r++) x[r] = __ldcs(s0 + lane + 32 * r);
        const unsigned v = decode_pack(x, lane);
        if (lane == 0) sm[0][g][role] = v;
    }
    __syncthreads();

    const unsigned va0 = sm[0][g][0];
    const unsigned vb0 = sm[0][g][1];
    const unsigned res0 = (role == 0) ? (va0 + vb0)   // LE carry == u32 add
                                      : (va0 ^ vb0);  // bytewise xor

    // ── Issue e1's raw loads as a batch BEFORE e0's stores ──
    float4 x1[8];
    if (has1) {
        const float4* __restrict__ s1 = srcbase + (size_t)e1 * 256;
        #pragma unroll
        for (int r = 0; r < 8; r++) x1[r] = __ldcs(s1 + lane + 32 * r);
    }

    // ── Store e0 output while e1's loads are in flight ──
    store_out(o4 + ((size_t)role * B + e0) * 256, res0, lane);

    // ── Phase 1 decode + store: element e1 ──
    if (has1) {
        const unsigned v = decode_pack(x1, lane);
        if (lane == 0) sm[1][g][role] = v;
    }
    __syncthreads();

    if (has1) {
        const unsigned va1 = sm[1][g][0];
        const unsigned vb1 = sm[1][g][1];
        const unsigned res1 = (role == 0) ? (va1 + vb1) : (va1 ^ vb1);
        store_out(o4 + ((size_t)role * B + e1) * 256, res1, lane);
    }
}

extern "C" void kernel_launch(void* const* d_in, const int* in_sizes, int n_in,
                              void* d_out, int out_size)
{
    const float4* a = (const float4*)d_in[0];
    const float4* b = (const float4*)d_in[1];
    float4* out = (float4*)d_out;

    const int B = in_sizes[0] / 1024;      // inputs are [B,4,256] floats
    const int blocks = (B + 7) / 8;        // 8 elements per 8-warp block
    moe_alu_kernel<<<blocks, 256>>>(a, b, out, B);
}